// round 5
// baseline (speedup 1.0000x reference)
#include <cuda_runtime.h>
#include <math.h>

// ---------------- problem constants ----------------
#define BB   32
#define TT   4096
#define AD   128
#define SS   100
#define BDM  10
#define HH   50
#define DD   30
#define CH   64            // chunk = 64 timesteps
#define NCH  (TT / CH)     // 64 chunks
#define RING 256           // 4-chunk smem ring (rows of t)
#define FULLM 0xffffffffu

// ---------------- global scratch ----------------
__device__ __align__(16) float g_z[(size_t)BB * TT * BDM];

// =====================================================================
// Kernel 1: z = mlp(x) only (sims moved into k_dp producers)
// =====================================================================
__global__ void k_project(const float* __restrict__ x,
                          const float* __restrict__ w1, const float* __restrict__ b1,
                          const float* __restrict__ w2, const float* __restrict__ b2,
                          const float* __restrict__ w3, const float* __restrict__ b3)
{
    __shared__ float w1s[BDM * AD];
    __shared__ float w2s[BDM * BDM], w3s[BDM * BDM];
    __shared__ float b1s[BDM], b2s[BDM], b3s[BDM];

    int tid = threadIdx.x;
    for (int i = tid; i < BDM * AD; i += 256) w1s[i] = w1[i];
    if (tid < BDM * BDM) { w2s[tid] = w2[tid]; w3s[tid] = w3[tid]; }
    if (tid < BDM) { b1s[tid] = b1[tid]; b2s[tid] = b2[tid]; b3s[tid] = b3[tid]; }
    __syncthreads();

    int gtid = blockIdx.x * 256 + tid;
    const float4* xr = (const float4*)(x + (size_t)gtid * AD);

    float z1[BDM];
#pragma unroll
    for (int d = 0; d < BDM; d++) z1[d] = b1s[d];

#pragma unroll 8
    for (int kk = 0; kk < AD / 4; ++kk) {
        float4 xv = xr[kk];
#pragma unroll
        for (int d = 0; d < BDM; d++) {
            float4 wv = ((const float4*)w1s)[d * (AD / 4) + kk];
            z1[d] += xv.x * wv.x + xv.y * wv.y + xv.z * wv.z + xv.w * wv.w;
        }
    }
#pragma unroll
    for (int d = 0; d < BDM; d++) z1[d] = fmaxf(z1[d], 0.0f);

    float z2[BDM];
#pragma unroll
    for (int d = 0; d < BDM; d++) {
        float a = b2s[d];
#pragma unroll
        for (int e = 0; e < BDM; e++) a += z1[e] * w2s[d * BDM + e];
        z2[d] = fmaxf(a, 0.0f);
    }
    float* zo = g_z + (size_t)gtid * BDM;
#pragma unroll
    for (int d = 0; d < BDM; d++) {
        float a = b3s[d];
#pragma unroll
        for (int e = 0; e < BDM; e++) a += z2[e] * w3s[d * BDM + e];
        zo[d] = a;
    }
}

// =====================================================================
// Kernel 2: fused sims-GEMM producers + skewed-wavefront DP consumer +
//           warp backtrack + segment mean + LSTM + head.
// 256 threads: warp0 = DP, warps 1-7 = producers.
// =====================================================================
struct SmemB {
    float4 simring[25 * RING];    // quad-major: [q][t&255]  (102,400 B)
    unsigned int bts[512 * 32];   // backtrack bits (65,536 B)
    float cq[BDM * SS];           // c staged (4000 B)
    float zstage[CH * BDM];       // z chunk (2560 B)
    float zz[SS * BDM];
    int bound[SS + 4];
    float hbuf[HH], cbuf[HH], gates[4 * HH];
    float rbuf[32], r2buf[32];
};

__device__ __forceinline__ float sigm(float v) { return 1.0f / (1.0f + __expf(-v)); }

// producer: compute sims for chunk cn into ring slot cn&3
__device__ __forceinline__ void produce_chunk(SmemB* sm, const float* __restrict__ zsrc,
                                              int p, int cn)
{
    const float* zg = zsrc + (size_t)cn * CH * BDM;
    for (int i = p; i < CH * BDM; i += 224) sm->zstage[i] = zg[i];
    asm volatile("bar.sync 1, 224;" ::: "memory");
    int rbase = (cn & 3) * CH;
    for (int i = p; i < CH * 25; i += 224) {
        int tr = i / 25;
        int q  = i - tr * 25;
        const float* zr = sm->zstage + tr * BDM;
        float4 a = make_float4(0.f, 0.f, 0.f, 0.f);
#pragma unroll
        for (int d = 0; d < BDM; d++) {
            float zv = zr[d];
            float4 cv = ((const float4*)sm->cq)[d * 25 + q];
            a.x += zv * cv.x; a.y += zv * cv.y;
            a.z += zv * cv.z; a.w += zv * cv.w;
        }
        sm->simring[q * RING + rbase + tr] = a;
    }
}

__global__ void __launch_bounds__(256, 1)
k_dp(const float* __restrict__ c,
     const float* __restrict__ w_ih, const float* __restrict__ w_hh,
     const float* __restrict__ b_ih, const float* __restrict__ b_hh,
     const float* __restrict__ wr1, const float* __restrict__ br1,
     const float* __restrict__ wr2, const float* __restrict__ br2,
     const float* __restrict__ wr3, const float* __restrict__ br3,
     float* __restrict__ out)
{
    extern __shared__ unsigned char smraw[];
    SmemB* sm = reinterpret_cast<SmemB*>(smraw);

    const int tid = threadIdx.x;
    const int b = blockIdx.x;
    const float* zsrc = g_z + (size_t)b * TT * BDM;

    // ---------------- prologue ----------------
    if (tid < 32) {
        for (int i = tid; i < SS * BDM; i += 32) sm->zz[i] = 0.0f;
        if (tid < 32) { /* hbuf/cbuf init below with HH=50 via 2 passes */ }
        for (int i = tid; i < HH; i += 32) { sm->hbuf[i] = 0.0f; sm->cbuf[i] = 0.0f; }
    } else {
        int p = tid - 32;
        for (int i = p; i < BDM * SS; i += 224) sm->cq[i] = c[i];
        produce_chunk(sm, zsrc, p, 0);   // also syncs producers via bar1
    }
    __syncthreads();

    // ---------------- DP state ----------------
    const int lane = tid & 31;
    const int qln = lane < 25 ? lane : 24;
    const float4* wrapptr = sm->simring + qln * RING;

    float st0 = 0.f, st1 = 0.f, st2 = 0.f, st3 = 0.f, st3p2 = 0.f;
    unsigned acc = 0;
    unsigned* btsp = sm->bts + lane;
    int nib = 0;

    // ---------------- block loop ----------------
    for (int k = 0; k < NCH; ++k) {
        if (tid < 32) {
            if (k == 0) {
                // specialized first block: walls 0..63, staggered start
                const float4* sp = wrapptr;
                for (int w = 0; w < 64; ++w) {
                    int t = w - lane;
                    float left = __shfl_up_sync(FULLM, st3p2, 1);
                    if (t >= 0) {
                        float4 sv = *sp;
                        if (t == 0) {
                            st0 = sv.x; st1 = sv.y; st2 = sv.z; st3 = sv.w;
                        } else {
                            if (lane == 0) left = 0.0f;
                            unsigned bb = (unsigned)(left > st0) | ((unsigned)(st0 > st1) << 1)
                                        | ((unsigned)(st1 > st2) << 2) | ((unsigned)(st2 > st3) << 3);
                            acc |= bb << ((t & 7) << 2);
                            float n0 = fmaxf(left, st0) + sv.x;
                            float n1 = fmaxf(st0, st1) + sv.y;
                            float n2 = fmaxf(st1, st2) + sv.z;
                            float n3 = fmaxf(st2, st3) + sv.w;
                            st3p2 = st3;
                            st0 = n0; st1 = n1; st2 = n2; st3 = n3;
                            if ((t & 7) == 7) { *btsp = acc; btsp += 32; acc = 0; }
                        }
                    }
                    sp = (((w + 1 - lane) & 255) == 0) ? wrapptr : sp + 1;
                }
                nib = ((64 - lane) & 7) << 2;
            } else {
                // steady-state block k: walls 64k .. 64k+63, all t valid
                int t0 = k * 64 - lane;
                float4 nxt  = wrapptr[t0 & 255];
                float4 nxt2 = wrapptr[(t0 + 1) & 255];
                int tm = (t0 + 2) & 255;
                const float4* sp2 = wrapptr + tm;
#pragma unroll 4
                for (int u = 0; u < 64; ++u) {
                    float4 sv = nxt; nxt = nxt2; nxt2 = *sp2;
                    tm = (tm + 1) & 255;
                    sp2 = (tm == 0) ? wrapptr : sp2 + 1;
                    float left = __shfl_up_sync(FULLM, st3p2, 1);
                    left = (lane == 0) ? 0.0f : left;
                    unsigned bb = (unsigned)(left > st0) | ((unsigned)(st0 > st1) << 1)
                                | ((unsigned)(st1 > st2) << 2) | ((unsigned)(st2 > st3) << 3);
                    acc |= bb << nib;
                    float n0 = fmaxf(left, st0) + sv.x;
                    float n1 = fmaxf(st0, st1) + sv.y;
                    float n2 = fmaxf(st1, st2) + sv.z;
                    float n3 = fmaxf(st2, st3) + sv.w;
                    st3p2 = st3;
                    st0 = n0; st1 = n1; st2 = n2; st3 = n3;
                    if (nib == 28) { *btsp = acc; btsp += 32; acc = 0; nib = 0; }
                    else nib += 4;
                }
            }
        } else {
            if (k + 1 < NCH) produce_chunk(sm, zsrc, tid - 32, k + 1);
        }
        __syncthreads();
    }

    // tail block: walls 4096..4126 drain lanes 1..31
    if (tid < 32) {
        for (int w = TT; w < TT + 31; ++w) {
            int t = w - lane;
            float left = __shfl_up_sync(FULLM, st3p2, 1);
            if (t < TT) {
                float4 sv = wrapptr[t & 255];
                if (lane == 0) left = 0.0f;
                unsigned bb = (unsigned)(left > st0) | ((unsigned)(st0 > st1) << 1)
                            | ((unsigned)(st1 > st2) << 2) | ((unsigned)(st2 > st3) << 3);
                acc |= bb << ((t & 7) << 2);
                float n0 = fmaxf(left, st0) + sv.x;
                float n1 = fmaxf(st0, st1) + sv.y;
                float n2 = fmaxf(st1, st2) + sv.z;
                float n3 = fmaxf(st2, st3) + sv.w;
                st3p2 = st3;
                st0 = n0; st1 = n1; st2 = n2; st3 = n3;
                if ((t & 7) == 7) { *btsp = acc; btsp += 32; acc = 0; }
            }
        }
    }
    __syncthreads();

    // ---------------- warp-parallel backtrack ----------------
    if (tid < 32) {
        int s = SS - 1, cur = TT - 1;
        while (s > 0) {
            int col = s >> 2, sub = s & 3;
            unsigned msk = 0x11111111u << sub;
            int gtop = cur >> 3;
            int ttstar = 0;
            for (int gb = gtop - 31; ; gb -= 32) {
                int g = gb + lane;
                unsigned w = 0;
                if (g >= 0 && g <= gtop) {
                    w = sm->bts[g * 32 + col] & msk;
                    if (g == gtop) {
                        int pm = cur & 7;
                        if (pm < 7) w &= (1u << ((pm + 1) * 4)) - 1u;
                    }
                }
                unsigned bal = __ballot_sync(FULLM, w != 0);
                if (bal) {
                    int hl = 31 - __clz((int)bal);
                    unsigned wh = __shfl_sync(FULLM, w, hl);
                    int hb = 31 - __clz((int)wh);
                    ttstar = (gb + hl) * 8 + (hb >> 2);
                    break;
                }
                if (gb <= 0 || gb * 8 <= s + 1) break;
            }
            int ttd = ttstar > s ? ttstar : s;
            if (lane == 0) sm->bound[s] = ttd;
            cur = ttd - 1;
            s--;
        }
        if (lane == 0) { sm->bound[0] = 0; sm->bound[SS] = TT; }
    }
    __syncthreads();

    // ---------------- segment sums ----------------
    {
        const int t0 = tid * (TT / 256);
        int lo = 0, hi = SS - 1;
        while (lo < hi) {
            int mid = (lo + hi + 1) >> 1;
            if (sm->bound[mid] <= t0) lo = mid; else hi = mid - 1;
        }
        int s = lo;
        int nxtb = sm->bound[s + 1];
        const float* zb = zsrc + (size_t)t0 * BDM;
        float av[BDM];
#pragma unroll
        for (int d = 0; d < BDM; d++) av[d] = 0.0f;

        for (int kk = 0; kk < TT / 256; ++kk) {
            int t = t0 + kk;
            if (t >= nxtb) {
#pragma unroll
                for (int d = 0; d < BDM; d++) {
                    atomicAdd(&sm->zz[s * BDM + d], av[d]);
                    av[d] = 0.0f;
                }
                s++;
                nxtb = sm->bound[s + 1];
            }
#pragma unroll
            for (int d = 0; d < BDM; d++) av[d] += zb[kk * BDM + d];
        }
#pragma unroll
        for (int d = 0; d < BDM; d++) atomicAdd(&sm->zz[s * BDM + d], av[d]);
    }
    __syncthreads();

    for (int i = tid; i < SS * BDM; i += 256) {
        int s = i / BDM;
        sm->zz[i] = sm->zz[i] / (float)(sm->bound[s + 1] - sm->bound[s]);
    }
    __syncthreads();

    // ---------------- LSTM (weights in registers) ----------------
    float whr[HH], wir[BDM], bsr = 0.0f;
    if (tid < 4 * HH) {
#pragma unroll
        for (int kk = 0; kk < HH; kk++) whr[kk] = w_hh[tid * HH + kk];
#pragma unroll
        for (int d = 0; d < BDM; d++) wir[d] = w_ih[tid * BDM + d];
        bsr = b_ih[tid] + b_hh[tid];
    }

    for (int stp = 0; stp < SS; ++stp) {
        if (tid < 4 * HH) {
            float g = bsr;
            const float* xt = sm->zz + stp * BDM;
#pragma unroll
            for (int d = 0; d < BDM; d++) g += wir[d] * xt[d];
#pragma unroll
            for (int kk = 0; kk < HH; kk++) g += whr[kk] * sm->hbuf[kk];
            sm->gates[tid] = g;
        }
        __syncthreads();
        if (tid < HH) {
            float iv = sm->gates[tid];
            float fv = sm->gates[HH + tid];
            float gv = sm->gates[2 * HH + tid];
            float ov = sm->gates[3 * HH + tid];
            float cc = sigm(fv) * sm->cbuf[tid] + sigm(iv) * tanhf(gv);
            sm->cbuf[tid] = cc;
            sm->hbuf[tid] = sigm(ov) * tanhf(cc);
        }
        __syncthreads();
    }

    // ---------------- MLP head ----------------
    if (tid < DD) {
        float r = br1[tid];
#pragma unroll 10
        for (int kk = 0; kk < HH; kk++) r += wr1[tid * HH + kk] * sm->hbuf[kk];
        sm->rbuf[tid] = fmaxf(r, 0.0f);
    }
    __syncthreads();
    if (tid < DD) {
        float r = br2[tid];
#pragma unroll
        for (int kk = 0; kk < DD; kk++) r += wr2[tid * DD + kk] * sm->rbuf[kk];
        sm->r2buf[tid] = fmaxf(r, 0.0f);
    }
    __syncthreads();
    if (tid == 0) {
        float r = br3[0];
#pragma unroll
        for (int d = 0; d < DD; d++) r += wr3[d] * sm->r2buf[d];
        out[b] = r;
    }
}

// =====================================================================
// launch
// =====================================================================
extern "C" void kernel_launch(void* const* d_in, const int* in_sizes, int n_in,
                              void* d_out, int out_size)
{
    (void)in_sizes; (void)n_in; (void)out_size;
    const float* x    = (const float*)d_in[0];
    const float* c    = (const float*)d_in[1];
    const float* w1   = (const float*)d_in[2];
    const float* b1   = (const float*)d_in[3];
    const float* w2   = (const float*)d_in[4];
    const float* b2   = (const float*)d_in[5];
    const float* w3   = (const float*)d_in[6];
    const float* b3   = (const float*)d_in[7];
    const float* w_ih = (const float*)d_in[8];
    const float* w_hh = (const float*)d_in[9];
    const float* b_ih = (const float*)d_in[10];
    const float* b_hh = (const float*)d_in[11];
    const float* wr1  = (const float*)d_in[12];
    const float* br1  = (const float*)d_in[13];
    const float* wr2  = (const float*)d_in[14];
    const float* br2  = (const float*)d_in[15];
    const float* wr3  = (const float*)d_in[16];
    const float* br3  = (const float*)d_in[17];
    float* out = (float*)d_out;

    cudaFuncSetAttribute(k_dp, cudaFuncAttributeMaxDynamicSharedMemorySize,
                         (int)sizeof(SmemB));

    k_project<<<(BB * TT) / 256, 256>>>(x, w1, b1, w2, b2, w3, b3);
    k_dp<<<BB, 256, sizeof(SmemB)>>>(c, w_ih, w_hh, b_ih, b_hh,
                                     wr1, br1, wr2, br2, wr3, br3, out);
}

// round 6
// speedup vs baseline: 1.0514x; 1.0514x over previous
#include <cuda_runtime.h>
#include <math.h>

// ---------------- problem constants ----------------
#define BB   32
#define TT   4096
#define AD   128
#define SS   100
#define BDM  10
#define HH   50
#define DD   30
#define CH   64            // chunk = 64 timesteps
#define NCH  (TT / CH)     // 64 chunks
#define RING 256           // 4-chunk ring
#define FULLM 0xffffffffu
#define NBTSW 516          // bts words per column (walls up to 4119 -> word 514)

// ---------------- global scratch ----------------
__device__ __align__(16) float g_z[(size_t)BB * TT * BDM];

// =====================================================================
// Kernel 1: z = mlp(x) only
// =====================================================================
__global__ void k_project(const float* __restrict__ x,
                          const float* __restrict__ w1, const float* __restrict__ b1,
                          const float* __restrict__ w2, const float* __restrict__ b2,
                          const float* __restrict__ w3, const float* __restrict__ b3)
{
    __shared__ float w1s[BDM * AD];
    __shared__ float w2s[BDM * BDM], w3s[BDM * BDM];
    __shared__ float b1s[BDM], b2s[BDM], b3s[BDM];

    int tid = threadIdx.x;
    for (int i = tid; i < BDM * AD; i += 256) w1s[i] = w1[i];
    if (tid < BDM * BDM) { w2s[tid] = w2[tid]; w3s[tid] = w3[tid]; }
    if (tid < BDM) { b1s[tid] = b1[tid]; b2s[tid] = b2[tid]; b3s[tid] = b3[tid]; }
    __syncthreads();

    int gtid = blockIdx.x * 256 + tid;
    const float4* xr = (const float4*)(x + (size_t)gtid * AD);

    float z1[BDM];
#pragma unroll
    for (int d = 0; d < BDM; d++) z1[d] = b1s[d];

#pragma unroll 8
    for (int kk = 0; kk < AD / 4; ++kk) {
        float4 xv = xr[kk];
#pragma unroll
        for (int d = 0; d < BDM; d++) {
            float4 wv = ((const float4*)w1s)[d * (AD / 4) + kk];
            z1[d] += xv.x * wv.x + xv.y * wv.y + xv.z * wv.z + xv.w * wv.w;
        }
    }
#pragma unroll
    for (int d = 0; d < BDM; d++) z1[d] = fmaxf(z1[d], 0.0f);

    float z2[BDM];
#pragma unroll
    for (int d = 0; d < BDM; d++) {
        float a = b2s[d];
#pragma unroll
        for (int e = 0; e < BDM; e++) a += z1[e] * w2s[d * BDM + e];
        z2[d] = fmaxf(a, 0.0f);
    }
    float* zo = g_z + (size_t)gtid * BDM;
#pragma unroll
    for (int d = 0; d < BDM; d++) {
        float a = b3s[d];
#pragma unroll
        for (int e = 0; e < BDM; e++) a += z2[e] * w3s[d * BDM + e];
        zo[d] = a;
    }
}

// =====================================================================
// Kernel 2
// warps: 7 = DP consumer (SMSP3 alone, highest priority)
//        {0,1,2,4,5,6} = producers (fused sims GEMM), 3 = init/idle
// Backtrack bit for (t, s): column col=s>>2, wall w=t+col,
// word w>>3, nibble w&7, bit s&3.
// =====================================================================
struct SmemB {
    float4 simring[25 * RING];     // 102,400 B quad-major
    unsigned int bts[NBTSW * 32];  //  66,048 B
    float cq[BDM * SS];
    float zstage[CH * BDM];
    float zz[SS * BDM];
    int bound[SS + 4];
    float hbuf[HH], cbuf[HH], gates[4 * HH];
    float rbuf[32], r2buf[32];
};

__device__ __forceinline__ float sigm(float v) { return 1.0f / (1.0f + __expf(-v)); }

__device__ __forceinline__ void produce_chunk(SmemB* sm, const float* __restrict__ zsrc,
                                              int p, int cn)
{
    const float* zg = zsrc + (size_t)cn * CH * BDM;
    for (int i = p; i < CH * BDM; i += 192) sm->zstage[i] = zg[i];
    asm volatile("bar.sync 1, 192;" ::: "memory");
    int rbase = (cn & 3) * CH;
    for (int i = p; i < CH * 25; i += 192) {
        int tr = i / 25;
        int q  = i - tr * 25;
        const float* zr = sm->zstage + tr * BDM;
        float4 a = make_float4(0.f, 0.f, 0.f, 0.f);
#pragma unroll
        for (int d = 0; d < BDM; d++) {
            float zv = zr[d];
            float4 cv = ((const float4*)sm->cq)[d * 25 + q];
            a.x += zv * cv.x; a.y += zv * cv.y;
            a.z += zv * cv.z; a.w += zv * cv.w;
        }
        sm->simring[q * RING + rbase + tr] = a;
    }
}

__global__ void __launch_bounds__(256, 1)
k_dp(const float* __restrict__ c,
     const float* __restrict__ w_ih, const float* __restrict__ w_hh,
     const float* __restrict__ b_ih, const float* __restrict__ b_hh,
     const float* __restrict__ wr1, const float* __restrict__ br1,
     const float* __restrict__ wr2, const float* __restrict__ br2,
     const float* __restrict__ wr3, const float* __restrict__ br3,
     float* __restrict__ out)
{
    extern __shared__ unsigned char smraw[];
    SmemB* sm = reinterpret_cast<SmemB*>(smraw);

    const int tid = threadIdx.x;
    const int b = blockIdx.x;
    const int wid = tid >> 5;
    const int lane = tid & 31;
    const bool cw = (wid == 7);                       // consumer warp
    const bool pw = (wid != 7 && wid != 3);           // producer warps
    const int pidx = pw ? (lane + 32 * (wid < 3 ? wid : wid - 1)) : 0;
    const float* zsrc = g_z + (size_t)b * TT * BDM;

    // ---------------- prologue ----------------
    if (wid == 3) {
        for (int i = lane; i < SS * BDM; i += 32) sm->zz[i] = 0.0f;
        for (int i = lane; i < HH; i += 32) { sm->hbuf[i] = 0.0f; sm->cbuf[i] = 0.0f; }
    } else if (pw) {
        for (int i = pidx; i < BDM * SS; i += 192) sm->cq[i] = c[i];
        produce_chunk(sm, zsrc, pidx, 0);
    }
    __syncthreads();

    // ---------------- DP state ----------------
    const int qln = lane < 25 ? lane : 24;
    const float4* wrapptr = sm->simring + qln * RING;
    float st0 = 0.f, st1 = 0.f, st2 = 0.f, st3 = 0.f, st3p2 = 0.f;

    // ---------------- block loop ----------------
    for (int k = 0; k < NCH; ++k) {
        if (cw) {
            if (k == 0) {
                unsigned acc = 0;
                for (int w = 0; w < 64; ++w) {
                    float left = __shfl_up_sync(FULLM, st3p2, 1);
                    int t = w - lane;
                    if (t >= 0) {
                        float4 sv = wrapptr[t];
                        if (t == 0) {
                            st0 = sv.x; st1 = sv.y; st2 = sv.z; st3 = sv.w;
                        } else {
                            if (lane == 0) left = 0.0f;
                            unsigned sh = (unsigned)((w & 7) << 2);
                            if (left > st0) acc |= 1u << sh;
                            if (st0 > st1)  acc |= 2u << sh;
                            if (st1 > st2)  acc |= 4u << sh;
                            if (st2 > st3)  acc |= 8u << sh;
                            float n0 = fmaxf(left, st0) + sv.x;
                            float n1 = fmaxf(st0, st1) + sv.y;
                            float n2 = fmaxf(st1, st2) + sv.z;
                            float n3 = fmaxf(st2, st3) + sv.w;
                            st3p2 = st3;
                            st0 = n0; st1 = n1; st2 = n2; st3 = n3;
                        }
                    }
                    if ((w & 7) == 7) { sm->bts[(w >> 3) * 32 + lane] = acc; acc = 0; }
                }
            } else {
                int tloc = (k * 64 - qln) & 255;
                float4 svn  = wrapptr[tloc];            tloc = (tloc + 1) & 255;
                float4 svn2 = wrapptr[tloc];            tloc = (tloc + 1) & 255;
                unsigned* btsp = sm->bts + (k * 8) * 32 + lane;
                for (int g8 = 0; g8 < 8; ++g8) {
                    unsigned acc = 0;
#pragma unroll
                    for (int u = 0; u < 8; ++u) {
                        float4 sv = svn; svn = svn2;
                        svn2 = wrapptr[tloc]; tloc = (tloc + 1) & 255;
                        float left = __shfl_up_sync(FULLM, st3p2, 1);
                        if (lane == 0) left = 0.0f;
                        if (left > st0) acc |= 1u << (u * 4);
                        if (st0 > st1)  acc |= 2u << (u * 4);
                        if (st1 > st2)  acc |= 4u << (u * 4);
                        if (st2 > st3)  acc |= 8u << (u * 4);
                        float n0 = fmaxf(left, st0) + sv.x;
                        float n1 = fmaxf(st0, st1) + sv.y;
                        float n2 = fmaxf(st1, st2) + sv.z;
                        float n3 = fmaxf(st2, st3) + sv.w;
                        st3p2 = st3;
                        st0 = n0; st1 = n1; st2 = n2; st3 = n3;
                    }
                    *btsp = acc; btsp += 32;
                }
            }
        } else if (pw) {
            if (k + 1 < NCH) produce_chunk(sm, zsrc, pidx, k + 1);
        }
        __syncthreads();
    }

    // ---------------- tail walls 4096..4119 ----------------
    if (cw) {
        unsigned acc = 0;
        for (int w = TT; w < TT + 24; ++w) {
            float left = __shfl_up_sync(FULLM, st3p2, 1);
            int t = w - lane;
            if (t <= TT - 1) {
                float4 sv = wrapptr[t & 255];
                if (lane == 0) left = 0.0f;
                unsigned sh = (unsigned)((w & 7) << 2);
                if (left > st0) acc |= 1u << sh;
                if (st0 > st1)  acc |= 2u << sh;
                if (st1 > st2)  acc |= 4u << sh;
                if (st2 > st3)  acc |= 8u << sh;
                float n0 = fmaxf(left, st0) + sv.x;
                float n1 = fmaxf(st0, st1) + sv.y;
                float n2 = fmaxf(st1, st2) + sv.z;
                float n3 = fmaxf(st2, st3) + sv.w;
                st3p2 = st3;
                st0 = n0; st1 = n1; st2 = n2; st3 = n3;
            }
            if ((w & 7) == 7) { sm->bts[(w >> 3) * 32 + lane] = acc; acc = 0; }
        }
    }
    __syncthreads();

    // ---------------- warp-parallel backtrack (wall-indexed) ----------------
    if (tid < 32) {
        int s = SS - 1, cur = TT - 1;
        while (s > 0) {
            int col = s >> 2, sub = s & 3;
            unsigned msk = 0x11111111u << sub;
            int curw = cur + col;
            int gtop = curw >> 3;
            int ttstar = 0;
            for (int gb = gtop - 31; ; gb -= 32) {
                int g = gb + lane;
                unsigned w = 0;
                if (g >= 0 && g <= gtop) {
                    w = sm->bts[g * 32 + col] & msk;
                    if (g == gtop) {
                        int pm = curw & 7;
                        if (pm < 7) w &= (1u << ((pm + 1) * 4)) - 1u;
                    }
                }
                unsigned bal = __ballot_sync(FULLM, w != 0);
                if (bal) {
                    int hl = 31 - __clz((int)bal);
                    unsigned wh = __shfl_sync(FULLM, w, hl);
                    int hb = 31 - __clz((int)wh);
                    ttstar = (gb + hl) * 8 + (hb >> 2) - col;
                    break;
                }
                if (gb <= 0 || gb * 8 <= s + 1 + col) break;
            }
            int ttd = ttstar > s ? ttstar : s;
            if (lane == 0) sm->bound[s] = ttd;
            cur = ttd - 1;
            s--;
        }
        if (lane == 0) { sm->bound[0] = 0; sm->bound[SS] = TT; }
    }
    __syncthreads();

    // ---------------- segment sums ----------------
    {
        const int t0 = tid * (TT / 256);
        int lo = 0, hi = SS - 1;
        while (lo < hi) {
            int mid = (lo + hi + 1) >> 1;
            if (sm->bound[mid] <= t0) lo = mid; else hi = mid - 1;
        }
        int s = lo;
        int nxtb = sm->bound[s + 1];
        const float* zb = zsrc + (size_t)t0 * BDM;
        float av[BDM];
#pragma unroll
        for (int d = 0; d < BDM; d++) av[d] = 0.0f;

        for (int kk = 0; kk < TT / 256; ++kk) {
            int t = t0 + kk;
            if (t >= nxtb) {
#pragma unroll
                for (int d = 0; d < BDM; d++) {
                    atomicAdd(&sm->zz[s * BDM + d], av[d]);
                    av[d] = 0.0f;
                }
                s++;
                nxtb = sm->bound[s + 1];
            }
#pragma unroll
            for (int d = 0; d < BDM; d++) av[d] += zb[kk * BDM + d];
        }
#pragma unroll
        for (int d = 0; d < BDM; d++) atomicAdd(&sm->zz[s * BDM + d], av[d]);
    }
    __syncthreads();

    for (int i = tid; i < SS * BDM; i += 256) {
        int s = i / BDM;
        sm->zz[i] = sm->zz[i] / (float)(sm->bound[s + 1] - sm->bound[s]);
    }
    __syncthreads();

    // ---------------- LSTM (weights in registers) ----------------
    float whr[HH], wir[BDM], bsr = 0.0f;
    if (tid < 4 * HH) {
#pragma unroll
        for (int kk = 0; kk < HH; kk++) whr[kk] = w_hh[tid * HH + kk];
#pragma unroll
        for (int d = 0; d < BDM; d++) wir[d] = w_ih[tid * BDM + d];
        bsr = b_ih[tid] + b_hh[tid];
    }

    for (int stp = 0; stp < SS; ++stp) {
        if (tid < 4 * HH) {
            float g = bsr;
            const float* xt = sm->zz + stp * BDM;
#pragma unroll
            for (int d = 0; d < BDM; d++) g += wir[d] * xt[d];
#pragma unroll
            for (int kk = 0; kk < HH; kk++) g += whr[kk] * sm->hbuf[kk];
            sm->gates[tid] = g;
        }
        __syncthreads();
        if (tid < HH) {
            float iv = sm->gates[tid];
            float fv = sm->gates[HH + tid];
            float gv = sm->gates[2 * HH + tid];
            float ov = sm->gates[3 * HH + tid];
            float cc = sigm(fv) * sm->cbuf[tid] + sigm(iv) * tanhf(gv);
            sm->cbuf[tid] = cc;
            sm->hbuf[tid] = sigm(ov) * tanhf(cc);
        }
        __syncthreads();
    }

    // ---------------- MLP head ----------------
    if (tid < DD) {
        float r = br1[tid];
#pragma unroll 10
        for (int kk = 0; kk < HH; kk++) r += wr1[tid * HH + kk] * sm->hbuf[kk];
        sm->rbuf[tid] = fmaxf(r, 0.0f);
    }
    __syncthreads();
    if (tid < DD) {
        float r = br2[tid];
#pragma unroll
        for (int kk = 0; kk < DD; kk++) r += wr2[tid * DD + kk] * sm->rbuf[kk];
        sm->r2buf[tid] = fmaxf(r, 0.0f);
    }
    __syncthreads();
    if (tid == 0) {
        float r = br3[0];
#pragma unroll
        for (int d = 0; d < DD; d++) r += wr3[d] * sm->r2buf[d];
        out[b] = r;
    }
}

// =====================================================================
// launch
// =====================================================================
extern "C" void kernel_launch(void* const* d_in, const int* in_sizes, int n_in,
                              void* d_out, int out_size)
{
    (void)in_sizes; (void)n_in; (void)out_size;
    const float* x    = (const float*)d_in[0];
    const float* c    = (const float*)d_in[1];
    const float* w1   = (const float*)d_in[2];
    const float* b1   = (const float*)d_in[3];
    const float* w2   = (const float*)d_in[4];
    const float* b2   = (const float*)d_in[5];
    const float* w3   = (const float*)d_in[6];
    const float* b3   = (const float*)d_in[7];
    const float* w_ih = (const float*)d_in[8];
    const float* w_hh = (const float*)d_in[9];
    const float* b_ih = (const float*)d_in[10];
    const float* b_hh = (const float*)d_in[11];
    const float* wr1  = (const float*)d_in[12];
    const float* br1  = (const float*)d_in[13];
    const float* wr2  = (const float*)d_in[14];
    const float* br2  = (const float*)d_in[15];
    const float* wr3  = (const float*)d_in[16];
    const float* br3  = (const float*)d_in[17];
    float* out = (float*)d_out;

    cudaFuncSetAttribute(k_dp, cudaFuncAttributeMaxDynamicSharedMemorySize,
                         (int)sizeof(SmemB));

    k_project<<<(BB * TT) / 256, 256>>>(x, w1, b1, w2, b2, w3, b3);
    k_dp<<<BB, 256, sizeof(SmemB)>>>(c, w_ih, w_hh, b_ih, b_hh,
                                     wr1, br1, wr2, br2, wr3, br3, out);
}

// round 7
// speedup vs baseline: 1.5237x; 1.4491x over previous
#include <cuda_runtime.h>
#include <math.h>

// ---------------- problem constants ----------------
#define BB   32
#define TT   4096
#define AD   128
#define SS   100
#define BDM  10
#define HH   50
#define DD   30
#define CH   64            // chunk = 64 timesteps
#define NCH  (TT / CH)     // 64 chunks
#define NQ   25            // S/4 float4 "quads"
#define TROW 65            // padded tile row (float4): 260 words = 4 mod 32 -> conflict-free phases
#define FULLM 0xffffffffu

// ---------------- global scratch ----------------
__device__ __align__(16) float4 g_simsT[(size_t)BB * NQ * TT];  // [b][q][t], 52.4 MB
__device__ __align__(16) float  g_z[(size_t)BB * TT * BDM];

// =====================================================================
// Kernel 1: z = mlp(x); sims stored quad-transposed [b][q][t] (coalesced)
// =====================================================================
__global__ void k_project(const float* __restrict__ x, const float* __restrict__ c,
                          const float* __restrict__ w1, const float* __restrict__ b1,
                          const float* __restrict__ w2, const float* __restrict__ b2,
                          const float* __restrict__ w3, const float* __restrict__ b3)
{
    __shared__ float w1s[BDM * AD];
    __shared__ float cs[BDM * SS];
    __shared__ float w2s[BDM * BDM], w3s[BDM * BDM];
    __shared__ float b1s[BDM], b2s[BDM], b3s[BDM];

    int tid = threadIdx.x;
    for (int i = tid; i < BDM * AD; i += 256) w1s[i] = w1[i];
    for (int i = tid; i < BDM * SS; i += 256) cs[i] = c[i];
    if (tid < BDM * BDM) { w2s[tid] = w2[tid]; w3s[tid] = w3[tid]; }
    if (tid < BDM) { b1s[tid] = b1[tid]; b2s[tid] = b2[tid]; b3s[tid] = b3[tid]; }
    __syncthreads();

    int gtid = blockIdx.x * 256 + tid;         // b*T + t
    int b = gtid >> 12;
    int t = gtid & (TT - 1);
    const float4* xr = (const float4*)(x + (size_t)gtid * AD);

    float z1[BDM];
#pragma unroll
    for (int d = 0; d < BDM; d++) z1[d] = b1s[d];

#pragma unroll 8
    for (int kk = 0; kk < AD / 4; ++kk) {
        float4 xv = xr[kk];
#pragma unroll
        for (int d = 0; d < BDM; d++) {
            float4 wv = ((const float4*)w1s)[d * (AD / 4) + kk];
            z1[d] += xv.x * wv.x + xv.y * wv.y + xv.z * wv.z + xv.w * wv.w;
        }
    }
#pragma unroll
    for (int d = 0; d < BDM; d++) z1[d] = fmaxf(z1[d], 0.0f);

    float z2[BDM];
#pragma unroll
    for (int d = 0; d < BDM; d++) {
        float a = b2s[d];
#pragma unroll
        for (int e = 0; e < BDM; e++) a += z1[e] * w2s[d * BDM + e];
        z2[d] = fmaxf(a, 0.0f);
    }
    float z3[BDM];
#pragma unroll
    for (int d = 0; d < BDM; d++) {
        float a = b3s[d];
#pragma unroll
        for (int e = 0; e < BDM; e++) a += z2[e] * w3s[d * BDM + e];
        z3[d] = a;
    }

    float* zo = g_z + (size_t)gtid * BDM;
#pragma unroll
    for (int d = 0; d < BDM; d++) zo[d] = z3[d];

#pragma unroll
    for (int q = 0; q < NQ; ++q) {
        float4 a = make_float4(0.f, 0.f, 0.f, 0.f);
#pragma unroll
        for (int d = 0; d < BDM; d++) {
            float zv = z3[d];
            float4 cv = ((const float4*)cs)[d * NQ + q];
            a.x += zv * cv.x; a.y += zv * cv.y;
            a.z += zv * cv.z; a.w += zv * cv.w;
        }
        g_simsT[((size_t)b * NQ + q) * TT + t] = a;   // coalesced over t
    }
}

// =====================================================================
// Kernel 2: R3 structure — warp0 consumer, warps1-7 copy producers,
// double-buffered quad-major tile. shfl software-pipelined (left_next).
// bts bit for (t,s): word t>>3, nibble t&7, column s>>2 (=lane), bit s&3.
// =====================================================================
struct SmemB {
    float4 tile[2][NQ * TROW];     // 52,000 B
    unsigned int bts[512 * 32];    // 65,536 B
    float zz[SS * BDM];
    int bound[SS + 4];
    float hbuf[HH], cbuf[HH], gates[4 * HH];
    float rbuf[32], r2buf[32];
};

__device__ __forceinline__ float sigm(float v) { return 1.0f / (1.0f + __expf(-v)); }

__device__ __forceinline__ void copy_chunk(SmemB* sm, int b, int p, int cn)
{
    float4* dst = sm->tile[cn & 1];
    for (int i = p; i < CH * NQ; i += 224) {
        int q = i >> 6;
        int r = i & 63;
        dst[q * TROW + r] = g_simsT[((size_t)b * NQ + q) * TT + cn * CH + r];
    }
}

// one DP step; nibble position U is compile-time
#define DPSTEP(sv, U) do {                                                       \
    float left = left_next;                                                      \
    if (lane == 0) left = 0.0f;                                                  \
    if (left > st0) acc |= 1u << ((U) * 4);                                      \
    if (st0 > st1)  acc |= 2u << ((U) * 4);                                      \
    if (st1 > st2)  acc |= 4u << ((U) * 4);                                      \
    if (st2 > st3)  acc |= 8u << ((U) * 4);                                      \
    float n0 = fmaxf(left, st0) + (sv).x;                                        \
    float n1 = fmaxf(st0, st1) + (sv).y;                                         \
    float n2 = fmaxf(st1, st2) + (sv).z;                                         \
    float n3 = fmaxf(st2, st3) + (sv).w;                                         \
    left_next = __shfl_up_sync(FULLM, n3, 1);                                    \
    st0 = n0; st1 = n1; st2 = n2; st3 = n3; } while (0)

__global__ void __launch_bounds__(256, 1)
k_dp(const float* __restrict__ w_ih, const float* __restrict__ w_hh,
     const float* __restrict__ b_ih, const float* __restrict__ b_hh,
     const float* __restrict__ wr1, const float* __restrict__ br1,
     const float* __restrict__ wr2, const float* __restrict__ br2,
     const float* __restrict__ wr3, const float* __restrict__ br3,
     float* __restrict__ out)
{
    extern __shared__ unsigned char smraw[];
    SmemB* sm = reinterpret_cast<SmemB*>(smraw);

    const int tid = threadIdx.x;
    const int b = blockIdx.x;
    const int lane = tid & 31;

    // ---- prologue: consumer inits, producers stage chunk 0 ----
    if (tid < 32) {
        for (int i = lane; i < SS * BDM; i += 32) sm->zz[i] = 0.0f;
        for (int i = lane; i < HH; i += 32) { sm->hbuf[i] = 0.0f; sm->cbuf[i] = 0.0f; }
    } else {
        copy_chunk(sm, b, tid - 32, 0);
    }
    __syncthreads();

    // ---- DP state ----
    const int qln = lane < NQ ? lane : NQ - 1;
    float st0 = 0.f, st1 = 0.f, st2 = 0.f, st3 = 0.f, left_next = 0.f;

    for (int ci = 0; ci < NCH; ++ci) {
        if (tid < 32) {
            const float4* tb = sm->tile[ci & 1] + qln * TROW;
            float4 nxt = tb[0];
            unsigned* bp = sm->bts + ci * 8 * 32 + lane;
            if (ci == 0) {
                // group 0 special: t=0 init, then t=1..7
                {
                    unsigned acc = 0;
                    float4 sv = nxt; nxt = tb[1];
                    st0 = sv.x; st1 = sv.y; st2 = sv.z; st3 = sv.w;
                    left_next = __shfl_up_sync(FULLM, st3, 1);
#pragma unroll
                    for (int u = 1; u < 8; ++u) {
                        sv = nxt; nxt = tb[u + 1];
                        DPSTEP(sv, u);
                    }
                    *bp = acc; bp += 32;
                }
                for (int g8 = 1; g8 < 8; ++g8) {
                    unsigned acc = 0;
                    const float4* tg = tb + g8 * 8;
#pragma unroll
                    for (int u = 0; u < 8; ++u) {
                        float4 sv = nxt; nxt = tg[u + 1];
                        DPSTEP(sv, u);
                    }
                    *bp = acc; bp += 32;
                }
            } else {
                for (int g8 = 0; g8 < 8; ++g8) {
                    unsigned acc = 0;
                    const float4* tg = tb + g8 * 8;
#pragma unroll
                    for (int u = 0; u < 8; ++u) {
                        float4 sv = nxt; nxt = tg[u + 1];   // tb[64] = pad, unused
                        DPSTEP(sv, u);
                    }
                    *bp = acc; bp += 32;
                }
            }
        } else {
            if (ci + 1 < NCH) copy_chunk(sm, b, tid - 32, ci + 1);
        }
        __syncthreads();
    }

    // ---------------- warp-parallel backtrack (t-indexed, R3) ----------------
    if (tid < 32) {
        int s = SS - 1, cur = TT - 1;
        while (s > 0) {
            int col = s >> 2, sub = s & 3;
            unsigned msk = 0x11111111u << sub;
            int gtop = cur >> 3;
            int ttstar = 0;
            for (int gb = gtop - 31; ; gb -= 32) {
                int g = gb + lane;
                unsigned w = 0;
                if (g >= 0 && g <= gtop) {
                    w = sm->bts[g * 32 + col] & msk;
                    if (g == gtop) {
                        int pm = cur & 7;
                        if (pm < 7) w &= (1u << ((pm + 1) * 4)) - 1u;
                    }
                }
                unsigned bal = __ballot_sync(FULLM, w != 0);
                if (bal) {
                    int hl = 31 - __clz((int)bal);
                    unsigned wh = __shfl_sync(FULLM, w, hl);
                    int hb = 31 - __clz((int)wh);
                    ttstar = (gb + hl) * 8 + (hb >> 2);
                    break;
                }
                if (gb <= 0 || gb * 8 <= s + 1) break;
            }
            int ttd = ttstar > s ? ttstar : s;
            if (lane == 0) sm->bound[s] = ttd;
            cur = ttd - 1;
            s--;
        }
        if (lane == 0) { sm->bound[0] = 0; sm->bound[SS] = TT; }
    }
    __syncthreads();

    // ---------------- segment sums ----------------
    {
        const int t0 = tid * (TT / 256);
        int lo = 0, hi = SS - 1;
        while (lo < hi) {
            int mid = (lo + hi + 1) >> 1;
            if (sm->bound[mid] <= t0) lo = mid; else hi = mid - 1;
        }
        int s = lo;
        int nxtb = sm->bound[s + 1];
        const float* zb = g_z + ((size_t)b * TT + t0) * BDM;
        float av[BDM];
#pragma unroll
        for (int d = 0; d < BDM; d++) av[d] = 0.0f;

        for (int kk = 0; kk < TT / 256; ++kk) {
            int t = t0 + kk;
            if (t >= nxtb) {
#pragma unroll
                for (int d = 0; d < BDM; d++) {
                    atomicAdd(&sm->zz[s * BDM + d], av[d]);
                    av[d] = 0.0f;
                }
                s++;
                nxtb = sm->bound[s + 1];
            }
#pragma unroll
            for (int d = 0; d < BDM; d++) av[d] += zb[kk * BDM + d];
        }
#pragma unroll
        for (int d = 0; d < BDM; d++) atomicAdd(&sm->zz[s * BDM + d], av[d]);
    }
    __syncthreads();

    for (int i = tid; i < SS * BDM; i += 256) {
        int s = i / BDM;
        sm->zz[i] = sm->zz[i] / (float)(sm->bound[s + 1] - sm->bound[s]);
    }
    __syncthreads();

    // ---------------- LSTM (weights in registers) ----------------
    float whr[HH], wir[BDM], bsr = 0.0f;
    if (tid < 4 * HH) {
#pragma unroll
        for (int kk = 0; kk < HH; kk++) whr[kk] = w_hh[tid * HH + kk];
#pragma unroll
        for (int d = 0; d < BDM; d++) wir[d] = w_ih[tid * BDM + d];
        bsr = b_ih[tid] + b_hh[tid];
    }

    for (int stp = 0; stp < SS; ++stp) {
        if (tid < 4 * HH) {
            float g = bsr;
            const float* xt = sm->zz + stp * BDM;
#pragma unroll
            for (int d = 0; d < BDM; d++) g += wir[d] * xt[d];
#pragma unroll
            for (int kk = 0; kk < HH; kk++) g += whr[kk] * sm->hbuf[kk];
            sm->gates[tid] = g;
        }
        __syncthreads();
        if (tid < HH) {
            float iv = sm->gates[tid];
            float fv = sm->gates[HH + tid];
            float gv = sm->gates[2 * HH + tid];
            float ov = sm->gates[3 * HH + tid];
            float cc = sigm(fv) * sm->cbuf[tid] + sigm(iv) * tanhf(gv);
            sm->cbuf[tid] = cc;
            sm->hbuf[tid] = sigm(ov) * tanhf(cc);
        }
        __syncthreads();
    }

    // ---------------- MLP head ----------------
    if (tid < DD) {
        float r = br1[tid];
#pragma unroll 10
        for (int kk = 0; kk < HH; kk++) r += wr1[tid * HH + kk] * sm->hbuf[kk];
        sm->rbuf[tid] = fmaxf(r, 0.0f);
    }
    __syncthreads();
    if (tid < DD) {
        float r = br2[tid];
#pragma unroll
        for (int kk = 0; kk < DD; kk++) r += wr2[tid * DD + kk] * sm->rbuf[kk];
        sm->r2buf[tid] = fmaxf(r, 0.0f);
    }
    __syncthreads();
    if (tid == 0) {
        float r = br3[0];
#pragma unroll
        for (int d = 0; d < DD; d++) r += wr3[d] * sm->r2buf[d];
        out[b] = r;
    }
}

// =====================================================================
// launch
// =====================================================================
extern "C" void kernel_launch(void* const* d_in, const int* in_sizes, int n_in,
                              void* d_out, int out_size)
{
    (void)in_sizes; (void)n_in; (void)out_size;
    const float* x    = (const float*)d_in[0];
    const float* c    = (const float*)d_in[1];
    const float* w1   = (const float*)d_in[2];
    const float* b1   = (const float*)d_in[3];
    const float* w2   = (const float*)d_in[4];
    const float* b2   = (const float*)d_in[5];
    const float* w3   = (const float*)d_in[6];
    const float* b3   = (const float*)d_in[7];
    const float* w_ih = (const float*)d_in[8];
    const float* w_hh = (const float*)d_in[9];
    const float* b_ih = (const float*)d_in[10];
    const float* b_hh = (const float*)d_in[11];
    const float* wr1  = (const float*)d_in[12];
    const float* br1  = (const float*)d_in[13];
    const float* wr2  = (const float*)d_in[14];
    const float* br2  = (const float*)d_in[15];
    const float* wr3  = (const float*)d_in[16];
    const float* br3  = (const float*)d_in[17];
    float* out = (float*)d_out;

    cudaFuncSetAttribute(k_dp, cudaFuncAttributeMaxDynamicSharedMemorySize,
                         (int)sizeof(SmemB));

    k_project<<<(BB * TT) / 256, 256>>>(x, c, w1, b1, w2, b2, w3, b3);
    k_dp<<<BB, 256, sizeof(SmemB)>>>(w_ih, w_hh, b_ih, b_hh,
                                     wr1, br1, wr2, br2, wr3, br3, out);
}